// round 3
// baseline (speedup 1.0000x reference)
#include <cuda_runtime.h>
#include <math.h>

// Problem constants (fixed shapes for this problem)
#define NMAX 100000
#define EMAX 3200000
#define POOL_BLOCKS 128

// ---------------- scratch (device globals; no allocation allowed) ------------
// float4 arrays guarantee the 16-byte alignment red.global.add.v4.f32 needs.
__device__ float  g_dinv[NMAX];                      // degree then rsqrt(deg+1)
__device__ int    g_src[EMAX];
__device__ int    g_dst[EMAX];
__device__ float4 g_scaled4[(size_t)NMAX * 16];      // (x@W) * dinv   (64 floats/node max)
__device__ float4 g_accum4 [(size_t)NMAX * 16];      // edge aggregation
__device__ float4 g_h4     [(size_t)NMAX * 16];      // layer output
__device__ float  g_partial[POOL_BLOCKS * 16];

// ---------------- small helpers ----------------------------------------------
__global__ void zero_dinv_kernel(int n) {
    int i = blockIdx.x * 256 + threadIdx.x;
    if (i < n) g_dinv[i] = 0.0f;
}

__global__ void zero_accum_kernel(int n4) {   // n4 = number of float4 elements
    int i = blockIdx.x * 256 + threadIdx.x;
    if (i < n4) g_accum4[i] = make_float4(0.f, 0.f, 0.f, 0.f);
}

// Copy int32 edge index into scratch and count in-degree (dst side).
// NOTE: edge_index is int32 on device (JAX default without x64), NOT int64.
__global__ void deg_convert_kernel(const int* __restrict__ ei, int E) {
    int e = blockIdx.x * 256 + threadIdx.x;
    if (e < E) {
        int s = ei[e];
        int d = ei[E + e];
        g_src[e] = s;
        g_dst[e] = d;
        atomicAdd(&g_dinv[d], 1.0f);   // exact integer counting in float
    }
}

__global__ void make_dinv_kernel(int n) {
    int i = blockIdx.x * 256 + threadIdx.x;
    if (i < n) g_dinv[i] = rsqrtf(g_dinv[i] + 1.0f);
}

// ---------------- GEMM + scale epilogue ---------------------------------------
// scaled[node,:] = (X[node,:] @ W) * dinv[node]
// One thread per node; full NOUT accumulator row in registers; W staged in
// shared in KC-row chunks (all lanes read the same W element -> LDS broadcast).
// X == nullptr means "read from g_h4".
template <int K, int NOUT, int KC>
__global__ void gemm_scaled_kernel(const float* __restrict__ X,
                                   const float* __restrict__ W,
                                   int n) {
    __shared__ float Wsh[KC * NOUT];
    const float4* X4 = X ? (const float4*)X : g_h4;
    int node = blockIdx.x * 256 + threadIdx.x;

    float acc[NOUT];
#pragma unroll
    for (int j = 0; j < NOUT; j++) acc[j] = 0.0f;

    for (int k0 = 0; k0 < K; k0 += KC) {
        __syncthreads();
        for (int i = threadIdx.x; i < KC * NOUT; i += 256)
            Wsh[i] = W[k0 * NOUT + i];
        __syncthreads();

        if (node < n) {
            for (int kb = 0; kb < KC; kb += 8) {
                float4 a = X4[(size_t)node * (K / 4) + (size_t)(k0 + kb) / 4];
                float4 b = X4[(size_t)node * (K / 4) + (size_t)(k0 + kb) / 4 + 1];
                float xr[8] = {a.x, a.y, a.z, a.w, b.x, b.y, b.z, b.w};
#pragma unroll
                for (int kk = 0; kk < 8; kk++) {
                    float xv = xr[kk];
                    const float* wrow = &Wsh[(kb + kk) * NOUT];
#pragma unroll
                    for (int j = 0; j < NOUT; j++)
                        acc[j] = fmaf(xv, wrow[j], acc[j]);
                }
            }
        }
    }

    if (node < n) {
        float dv = g_dinv[node];
#pragma unroll
        for (int j = 0; j < NOUT; j += 4) {
            float4 v;
            v.x = acc[j + 0] * dv;
            v.y = acc[j + 1] * dv;
            v.z = acc[j + 2] * dv;
            v.w = acc[j + 3] * dv;
            g_scaled4[((size_t)node * NOUT + j) / 4] = v;
        }
    }
}

// ---------------- edge gather + scatter-add -----------------------------------
// accum[dst,:] += scaled[src,:]   (vectorized float4 reduction atomics)
template <int NOUT>
__global__ void scatter_edges_kernel(int E) {
    constexpr int CH = NOUT / 4;                       // float4 chunks per row
    long long idx = (long long)blockIdx.x * 256 + threadIdx.x;
    long long total = (long long)E * CH;
    if (idx >= total) return;
    int e = (int)(idx / CH);
    int c = (int)(idx % CH);
    int s = g_src[e];
    int d = g_dst[e];
    float4 v = g_scaled4[(size_t)s * CH + c];
    float4* p = &g_accum4[(size_t)d * CH + c];
    asm volatile("red.global.add.v4.f32 [%0], {%1,%2,%3,%4};"
                 :: "l"(p), "f"(v.x), "f"(v.y), "f"(v.z), "f"(v.w)
                 : "memory");
}

// ---------------- layer epilogue ----------------------------------------------
// h = relu(dinv[n] * (accum + scaled) + b)
template <int NOUT>
__global__ void finalize_kernel(const float* __restrict__ bias, int n) {
    constexpr int CH = NOUT / 4;
    int i = blockIdx.x * 256 + threadIdx.x;
    if (i >= n * CH) return;
    int node = i / CH;
    int c = i % CH;
    float dv = g_dinv[node];
    float4 a = g_accum4[i];
    float4 s = g_scaled4[i];
    float4 b = ((const float4*)bias)[c];
    float4 r;
    r.x = fmaxf(fmaf(dv, a.x + s.x, b.x), 0.0f);
    r.y = fmaxf(fmaf(dv, a.y + s.y, b.y), 0.0f);
    r.z = fmaxf(fmaf(dv, a.z + s.z, b.z), 0.0f);
    r.w = fmaxf(fmaf(dv, a.w + s.w, b.w), 0.0f);
    g_h4[i] = r;
}

// ---------------- pooling (deterministic two-stage) ---------------------------
__global__ void pool_partial_kernel(int n) {
    __shared__ float s[256];
    const float* h = (const float*)g_h4;
    int f = threadIdx.x & 15;
    int grp = threadIdx.x >> 4;
    int chunk = (n + POOL_BLOCKS - 1) / POOL_BLOCKS;
    int start = blockIdx.x * chunk;
    int end = min(start + chunk, n);
    float sum = 0.0f;
    for (int node = start + grp; node < end; node += 16)
        sum += h[(size_t)node * 16 + f];
    s[threadIdx.x] = sum;
    __syncthreads();
    for (int off = 128; off >= 16; off >>= 1) {
        if (threadIdx.x < off) s[threadIdx.x] += s[threadIdx.x + off];
        __syncthreads();
    }
    if (threadIdx.x < 16) g_partial[blockIdx.x * 16 + threadIdx.x] = s[threadIdx.x];
}

// pooled -> relu(pooled@Wf+bf) -> @Ws+bs -> log_softmax
__global__ void final_mlp_kernel(const float* __restrict__ Wf, const float* __restrict__ bf,
                                 const float* __restrict__ Ws, const float* __restrict__ bs,
                                 float* __restrict__ out, int n) {
    __shared__ float pooled[16];
    __shared__ float hidden[8];
    __shared__ float scores[10];
    int t = threadIdx.x;   // 32 threads
    if (t < 16) {
        float sum = 0.0f;
        for (int b = 0; b < POOL_BLOCKS; b++) sum += g_partial[b * 16 + t];
        pooled[t] = sum / (float)n;
    }
    __syncthreads();
    if (t < 8) {
        float a = bf[t];
        for (int k = 0; k < 16; k++) a = fmaf(pooled[k], Wf[k * 8 + t], a);
        hidden[t] = fmaxf(a, 0.0f);
    }
    __syncthreads();
    if (t < 10) {
        float a = bs[t];
        for (int k = 0; k < 8; k++) a = fmaf(hidden[k], Ws[k * 10 + t], a);
        scores[t] = a;
    }
    __syncthreads();
    if (t == 0) {
        float m = scores[0];
        for (int j = 1; j < 10; j++) m = fmaxf(m, scores[j]);
        float sum = 0.0f;
        for (int j = 0; j < 10; j++) sum += expf(scores[j] - m);
        float lse = m + logf(sum);
        for (int j = 0; j < 10; j++) out[j] = scores[j] - lse;
    }
}

// ---------------- launch ------------------------------------------------------
extern "C" void kernel_launch(void* const* d_in, const int* in_sizes, int n_in,
                              void* d_out, int out_size) {
    const float* features = (const float*)d_in[0];
    const int*   ei       = (const int*)d_in[1];   // int32! (JAX default integer width)
    const float* W1 = (const float*)d_in[2];  const float* b1 = (const float*)d_in[3];
    const float* W2 = (const float*)d_in[4];  const float* b2 = (const float*)d_in[5];
    const float* W3 = (const float*)d_in[6];  const float* b3 = (const float*)d_in[7];
    const float* Wf = (const float*)d_in[8];  const float* bf = (const float*)d_in[9];
    const float* Ws = (const float*)d_in[10]; const float* bs = (const float*)d_in[11];

    int N = in_sizes[0] / 256;
    int E = in_sizes[1] / 2;

    int nbN = (N + 255) / 256;
    int nbE = (E + 255) / 256;

    // degree / normalization
    zero_dinv_kernel<<<nbN, 256>>>(N);
    deg_convert_kernel<<<nbE, 256>>>(ei, E);
    make_dinv_kernel<<<nbN, 256>>>(N);

    // ---- layer 1: 256 -> 64 ----
    {
        int n4 = N * 16;
        zero_accum_kernel<<<(n4 + 255) / 256, 256>>>(n4);
        gemm_scaled_kernel<256, 64, 128><<<nbN, 256>>>(features, W1, N);
        long long tot = (long long)E * 16;
        scatter_edges_kernel<64><<<(int)((tot + 255) / 256), 256>>>(E);
        finalize_kernel<64><<<(N * 16 + 255) / 256, 256>>>(b1, N);
    }
    // ---- layer 2: 64 -> 32 ----
    {
        int n4 = N * 8;
        zero_accum_kernel<<<(n4 + 255) / 256, 256>>>(n4);
        gemm_scaled_kernel<64, 32, 64><<<nbN, 256>>>(nullptr, W2, N);
        long long tot = (long long)E * 8;
        scatter_edges_kernel<32><<<(int)((tot + 255) / 256), 256>>>(E);
        finalize_kernel<32><<<(N * 8 + 255) / 256, 256>>>(b2, N);
    }
    // ---- layer 3: 32 -> 16 ----
    {
        int n4 = N * 4;
        zero_accum_kernel<<<(n4 + 255) / 256, 256>>>(n4);
        gemm_scaled_kernel<32, 16, 32><<<nbN, 256>>>(nullptr, W3, N);
        long long tot = (long long)E * 4;
        scatter_edges_kernel<16><<<(int)((tot + 255) / 256), 256>>>(E);
        finalize_kernel<16><<<(N * 4 + 255) / 256, 256>>>(b3, N);
    }

    // ---- pooling + MLP head ----
    pool_partial_kernel<<<POOL_BLOCKS, 256>>>(N);
    final_mlp_kernel<<<1, 32>>>(Wf, bf, Ws, bs, (float*)d_out, N);
}

// round 4
// speedup vs baseline: 1.4468x; 1.4468x over previous
#include <cuda_runtime.h>
#include <math.h>

// Problem constants (fixed shapes for this problem)
#define NMAX 100000
#define EMAX 3200000
#define POOL_BLOCKS 128
#define SCAN_B 1024
#define SCAN_NB ((NMAX + SCAN_B - 1) / SCAN_B)   // 98

// ---------------- scratch (device globals; no allocation allowed) ------------
__device__ int    g_deg[NMAX];                       // in-degree (int)
__device__ int    g_off[NMAX];                       // CSR exclusive offsets
__device__ int    g_cursor[NMAX];                    // fill cursors
__device__ int    g_csr_src[EMAX];                   // src ids, grouped by dst
__device__ int    g_blocksum[128];                   // scan partials
__device__ float  g_dinv[NMAX];                      // rsqrt(deg+1)
__device__ float4 g_scaled4[(size_t)NMAX * 16];      // (x@W) * dinv
__device__ float4 g_h4     [(size_t)NMAX * 16];      // layer output
__device__ float  g_partial[POOL_BLOCKS * 16];

// ---------------- degree / CSR construction ----------------------------------
__global__ void zero_deg_kernel(int n) {
    int i = blockIdx.x * 256 + threadIdx.x;
    if (i < n) g_deg[i] = 0;
}

__global__ void deg_count_kernel(const int* __restrict__ ei, int E) {
    int e = blockIdx.x * 256 + threadIdx.x;
    if (e < E) atomicAdd(&g_deg[ei[E + e]], 1);
}

__global__ void make_dinv_kernel(int n) {
    int i = blockIdx.x * 256 + threadIdx.x;
    if (i < n) g_dinv[i] = rsqrtf((float)g_deg[i] + 1.0f);
}

// Block-level exclusive scan of g_deg -> g_off, block totals -> g_blocksum.
__global__ void scan1_kernel(int n) {
    __shared__ int sh[SCAN_B];
    int i = blockIdx.x * SCAN_B + threadIdx.x;
    int v = (i < n) ? g_deg[i] : 0;
    sh[threadIdx.x] = v;
    __syncthreads();
    for (int off = 1; off < SCAN_B; off <<= 1) {
        int t = (threadIdx.x >= off) ? sh[threadIdx.x - off] : 0;
        __syncthreads();
        sh[threadIdx.x] += t;
        __syncthreads();
    }
    if (i < n) g_off[i] = sh[threadIdx.x] - v;          // exclusive
    if (threadIdx.x == SCAN_B - 1) g_blocksum[blockIdx.x] = sh[SCAN_B - 1];
}

// Single-block exclusive scan of the <=128 block totals.
__global__ void scan2_kernel(int nb) {
    __shared__ int sh[128];
    int v = (threadIdx.x < nb) ? g_blocksum[threadIdx.x] : 0;
    sh[threadIdx.x] = v;
    __syncthreads();
    for (int off = 1; off < 128; off <<= 1) {
        int t = (threadIdx.x >= off) ? sh[threadIdx.x - off] : 0;
        __syncthreads();
        sh[threadIdx.x] += t;
        __syncthreads();
    }
    if (threadIdx.x < nb) g_blocksum[threadIdx.x] = sh[threadIdx.x] - v;  // exclusive
}

__global__ void scan3_kernel(int n) {
    int i = blockIdx.x * SCAN_B + threadIdx.x;
    if (i < n) {
        int o = g_off[i] + g_blocksum[blockIdx.x];
        g_off[i] = o;
        g_cursor[i] = o;
    }
}

__global__ void csr_fill_kernel(const int* __restrict__ ei, int E) {
    int e = blockIdx.x * 256 + threadIdx.x;
    if (e < E) {
        int s = ei[e];
        int d = ei[E + e];
        int pos = atomicAdd(&g_cursor[d], 1);
        g_csr_src[pos] = s;
    }
}

// ---------------- GEMM + scale epilogue ---------------------------------------
// scaled[node,:] = (X[node,:] @ W) * dinv[node]
// One thread per node; full NOUT accumulator row in registers; W staged in
// shared (LDS broadcast reads). X == nullptr means "read from g_h4".
template <int K, int NOUT, int KC>
__global__ void gemm_scaled_kernel(const float* __restrict__ X,
                                   const float* __restrict__ W,
                                   int n) {
    __shared__ float Wsh[KC * NOUT];
    const float4* X4 = X ? (const float4*)X : g_h4;
    int node = blockIdx.x * 256 + threadIdx.x;

    float acc[NOUT];
#pragma unroll
    for (int j = 0; j < NOUT; j++) acc[j] = 0.0f;

    for (int k0 = 0; k0 < K; k0 += KC) {
        __syncthreads();
        for (int i = threadIdx.x; i < KC * NOUT; i += 256)
            Wsh[i] = W[k0 * NOUT + i];
        __syncthreads();

        if (node < n) {
            for (int kb = 0; kb < KC; kb += 8) {
                float4 a = X4[(size_t)node * (K / 4) + (size_t)(k0 + kb) / 4];
                float4 b = X4[(size_t)node * (K / 4) + (size_t)(k0 + kb) / 4 + 1];
                float xr[8] = {a.x, a.y, a.z, a.w, b.x, b.y, b.z, b.w};
#pragma unroll
                for (int kk = 0; kk < 8; kk++) {
                    float xv = xr[kk];
                    const float* wrow = &Wsh[(kb + kk) * NOUT];
#pragma unroll
                    for (int j = 0; j < NOUT; j++)
                        acc[j] = fmaf(xv, wrow[j], acc[j]);
                }
            }
        }
    }

    if (node < n) {
        float dv = g_dinv[node];
#pragma unroll
        for (int j = 0; j < NOUT; j += 4) {
            float4 v;
            v.x = acc[j + 0] * dv;
            v.y = acc[j + 1] * dv;
            v.z = acc[j + 2] * dv;
            v.w = acc[j + 3] * dv;
            g_scaled4[((size_t)node * NOUT + j) / 4] = v;
        }
    }
}

// ---------------- fused pull-aggregate + finalize -----------------------------
// h[n] = relu(dinv[n] * (sum_{e in CSR[n]} scaled[src_e] + scaled[n]) + bias)
// CH threads cooperate on one node (one float4 column each). Edge loop unrolled
// x4 for MLP. No atomics, no zero pass, no separate finalize.
template <int NOUT>
__global__ void aggregate_kernel(const float* __restrict__ bias, int n) {
    constexpr int CH = NOUT / 4;                 // threads per node
    constexpr int NPB = 256 / CH;                // nodes per block
    int node = blockIdx.x * NPB + threadIdx.x / CH;
    int c = threadIdx.x % CH;
    if (node >= n) return;

    int start = g_off[node];
    int end = start + g_deg[node];

    float4 acc = g_scaled4[(size_t)node * CH + c];   // self-loop term

    int e = start;
    for (; e + 4 <= end; e += 4) {
        int s0 = g_csr_src[e + 0];
        int s1 = g_csr_src[e + 1];
        int s2 = g_csr_src[e + 2];
        int s3 = g_csr_src[e + 3];
        float4 v0 = g_scaled4[(size_t)s0 * CH + c];
        float4 v1 = g_scaled4[(size_t)s1 * CH + c];
        float4 v2 = g_scaled4[(size_t)s2 * CH + c];
        float4 v3 = g_scaled4[(size_t)s3 * CH + c];
        acc.x += (v0.x + v1.x) + (v2.x + v3.x);
        acc.y += (v0.y + v1.y) + (v2.y + v3.y);
        acc.z += (v0.z + v1.z) + (v2.z + v3.z);
        acc.w += (v0.w + v1.w) + (v2.w + v3.w);
    }
    for (; e < end; e++) {
        int s = g_csr_src[e];
        float4 v = g_scaled4[(size_t)s * CH + c];
        acc.x += v.x; acc.y += v.y; acc.z += v.z; acc.w += v.w;
    }

    float dv = g_dinv[node];
    float4 b = ((const float4*)bias)[c];
    float4 r;
    r.x = fmaxf(fmaf(dv, acc.x, b.x), 0.0f);
    r.y = fmaxf(fmaf(dv, acc.y, b.y), 0.0f);
    r.z = fmaxf(fmaf(dv, acc.z, b.z), 0.0f);
    r.w = fmaxf(fmaf(dv, acc.w, b.w), 0.0f);
    g_h4[(size_t)node * CH + c] = r;
}

// ---------------- pooling (deterministic two-stage) ---------------------------
__global__ void pool_partial_kernel(int n) {
    __shared__ float s[256];
    const float* h = (const float*)g_h4;
    int f = threadIdx.x & 15;
    int grp = threadIdx.x >> 4;
    int chunk = (n + POOL_BLOCKS - 1) / POOL_BLOCKS;
    int start = blockIdx.x * chunk;
    int end = min(start + chunk, n);
    float sum = 0.0f;
    for (int node = start + grp; node < end; node += 16)
        sum += h[(size_t)node * 16 + f];
    s[threadIdx.x] = sum;
    __syncthreads();
    for (int off = 128; off >= 16; off >>= 1) {
        if (threadIdx.x < off) s[threadIdx.x] += s[threadIdx.x + off];
        __syncthreads();
    }
    if (threadIdx.x < 16) g_partial[blockIdx.x * 16 + threadIdx.x] = s[threadIdx.x];
}

// pooled -> relu(pooled@Wf+bf) -> @Ws+bs -> log_softmax
__global__ void final_mlp_kernel(const float* __restrict__ Wf, const float* __restrict__ bf,
                                 const float* __restrict__ Ws, const float* __restrict__ bs,
                                 float* __restrict__ out, int n) {
    __shared__ float pooled[16];
    __shared__ float hidden[8];
    __shared__ float scores[10];
    int t = threadIdx.x;   // 32 threads
    if (t < 16) {
        float sum = 0.0f;
        for (int b = 0; b < POOL_BLOCKS; b++) sum += g_partial[b * 16 + t];
        pooled[t] = sum / (float)n;
    }
    __syncthreads();
    if (t < 8) {
        float a = bf[t];
        for (int k = 0; k < 16; k++) a = fmaf(pooled[k], Wf[k * 8 + t], a);
        hidden[t] = fmaxf(a, 0.0f);
    }
    __syncthreads();
    if (t < 10) {
        float a = bs[t];
        for (int k = 0; k < 8; k++) a = fmaf(hidden[k], Ws[k * 10 + t], a);
        scores[t] = a;
    }
    __syncthreads();
    if (t == 0) {
        float m = scores[0];
        for (int j = 1; j < 10; j++) m = fmaxf(m, scores[j]);
        float sum = 0.0f;
        for (int j = 0; j < 10; j++) sum += expf(scores[j] - m);
        float lse = m + logf(sum);
        for (int j = 0; j < 10; j++) out[j] = scores[j] - lse;
    }
}

// ---------------- launch ------------------------------------------------------
extern "C" void kernel_launch(void* const* d_in, const int* in_sizes, int n_in,
                              void* d_out, int out_size) {
    const float* features = (const float*)d_in[0];
    const int*   ei       = (const int*)d_in[1];   // int32 (JAX default int width)
    const float* W1 = (const float*)d_in[2];  const float* b1 = (const float*)d_in[3];
    const float* W2 = (const float*)d_in[4];  const float* b2 = (const float*)d_in[5];
    const float* W3 = (const float*)d_in[6];  const float* b3 = (const float*)d_in[7];
    const float* Wf = (const float*)d_in[8];  const float* bf = (const float*)d_in[9];
    const float* Ws = (const float*)d_in[10]; const float* bs = (const float*)d_in[11];

    int N = in_sizes[0] / 256;
    int E = in_sizes[1] / 2;

    int nbN = (N + 255) / 256;
    int nbE = (E + 255) / 256;
    int nbScan = (N + SCAN_B - 1) / SCAN_B;

    // ---- CSR build (once per launch, reused by all 3 layers) ----
    zero_deg_kernel<<<nbN, 256>>>(N);
    deg_count_kernel<<<nbE, 256>>>(ei, E);
    make_dinv_kernel<<<nbN, 256>>>(N);
    scan1_kernel<<<nbScan, SCAN_B>>>(N);
    scan2_kernel<<<1, 128>>>(nbScan);
    scan3_kernel<<<nbScan, SCAN_B>>>(N);
    csr_fill_kernel<<<nbE, 256>>>(ei, E);

    // ---- layer 1: 256 -> 64 ----
    gemm_scaled_kernel<256, 64, 128><<<nbN, 256>>>(features, W1, N);
    aggregate_kernel<64><<<(N * 16 + 255) / 256, 256>>>(b1, N);

    // ---- layer 2: 64 -> 32 ----
    gemm_scaled_kernel<64, 32, 64><<<nbN, 256>>>(nullptr, W2, N);
    aggregate_kernel<32><<<(N * 8 + 255) / 256, 256>>>(b2, N);

    // ---- layer 3: 32 -> 16 ----
    gemm_scaled_kernel<32, 16, 32><<<nbN, 256>>>(nullptr, W3, N);
    aggregate_kernel<16><<<(N * 4 + 255) / 256, 256>>>(b3, N);

    // ---- pooling + MLP head ----
    pool_partial_kernel<<<POOL_BLOCKS, 256>>>(N);
    final_mlp_kernel<<<1, 32>>>(Wf, bf, Ws, bs, (float*)d_out, N);
}

// round 5
// speedup vs baseline: 1.6147x; 1.1161x over previous
#include <cuda_runtime.h>
#include <math.h>

// Problem constants (fixed shapes for this problem)
#define NMAX 100000
#define EMAX 3200000
#define POOL_BLOCKS 128
#define SCAN_B 1024

// ---------------- scratch (device globals; no allocation allowed) ------------
__device__ int    g_deg[NMAX];                       // in-degree (int)
__device__ int    g_off[NMAX];                       // CSR exclusive offsets
__device__ int    g_cursor[NMAX];                    // fill cursors
__device__ int    g_csr_src[EMAX];                   // src ids, grouped by dst
__device__ int    g_blocksum[128];                   // scan partials
__device__ float  g_dinv[NMAX];                      // rsqrt(deg+1)
__device__ float4 g_scaled4[(size_t)NMAX * 16];      // (x@W) * dinv
__device__ float4 g_h4     [(size_t)NMAX * 16];      // layer output
__device__ float  g_partial[POOL_BLOCKS * 16];

// ---------------- packed f32x2 helpers (Blackwell: 2 FMAs / instruction) -----
__device__ __forceinline__ unsigned long long pack_f32x2(float lo, float hi) {
    unsigned long long r;
    asm("mov.b64 %0, {%1, %2};" : "=l"(r) : "f"(lo), "f"(hi));
    return r;
}
__device__ __forceinline__ void fma_f32x2(unsigned long long& d,
                                          unsigned long long a,
                                          unsigned long long b) {
    asm("fma.rn.f32x2 %0, %1, %2, %0;" : "+l"(d) : "l"(a), "l"(b));
}
__device__ __forceinline__ void unpack_f32x2(float& lo, float& hi, unsigned long long v) {
    asm("mov.b64 {%0, %1}, %2;" : "=f"(lo), "=f"(hi) : "l"(v));
}

// ---------------- degree / CSR construction ----------------------------------
__global__ void zero_deg_kernel(int n) {
    int i = blockIdx.x * 256 + threadIdx.x;
    if (i < n) g_deg[i] = 0;
}

__global__ void deg_count_kernel(const int* __restrict__ ei, int E) {
    int e = blockIdx.x * 256 + threadIdx.x;
    if (e < E) atomicAdd(&g_deg[ei[E + e]], 1);
}

__global__ void make_dinv_kernel(int n) {
    int i = blockIdx.x * 256 + threadIdx.x;
    if (i < n) g_dinv[i] = rsqrtf((float)g_deg[i] + 1.0f);
}

// Block-level exclusive scan of g_deg -> g_off, block totals -> g_blocksum.
__global__ void scan1_kernel(int n) {
    __shared__ int sh[SCAN_B];
    int i = blockIdx.x * SCAN_B + threadIdx.x;
    int v = (i < n) ? g_deg[i] : 0;
    sh[threadIdx.x] = v;
    __syncthreads();
    for (int off = 1; off < SCAN_B; off <<= 1) {
        int t = (threadIdx.x >= off) ? sh[threadIdx.x - off] : 0;
        __syncthreads();
        sh[threadIdx.x] += t;
        __syncthreads();
    }
    if (i < n) g_off[i] = sh[threadIdx.x] - v;          // exclusive
    if (threadIdx.x == SCAN_B - 1) g_blocksum[blockIdx.x] = sh[SCAN_B - 1];
}

__global__ void scan2_kernel(int nb) {
    __shared__ int sh[128];
    int v = (threadIdx.x < nb) ? g_blocksum[threadIdx.x] : 0;
    sh[threadIdx.x] = v;
    __syncthreads();
    for (int off = 1; off < 128; off <<= 1) {
        int t = (threadIdx.x >= off) ? sh[threadIdx.x - off] : 0;
        __syncthreads();
        sh[threadIdx.x] += t;
        __syncthreads();
    }
    if (threadIdx.x < nb) g_blocksum[threadIdx.x] = sh[threadIdx.x] - v;  // exclusive
}

__global__ void scan3_kernel(int n) {
    int i = blockIdx.x * SCAN_B + threadIdx.x;
    if (i < n) {
        int o = g_off[i] + g_blocksum[blockIdx.x];
        g_off[i] = o;
        g_cursor[i] = o;
    }
}

__global__ void csr_fill_kernel(const int* __restrict__ ei, int E) {
    int e = blockIdx.x * 256 + threadIdx.x;
    if (e < E) {
        int s = ei[e];
        int d = ei[E + e];
        int pos = atomicAdd(&g_cursor[d], 1);
        g_csr_src[pos] = s;
    }
}

// ---------------- GEMM + scale epilogue (packed f32x2 math) -------------------
// scaled[node,:] = (X[node,:] @ W) * dinv[node]
// One thread per node; NOUT/2 packed f32x2 accumulators; W staged in shared and
// read as 128-bit ulonglong2 (2 packed pairs per LDS.128, broadcast).
// X == nullptr means "read from g_h4".
template <int K, int NOUT, int KC>
__global__ void gemm_scaled_kernel(const float* __restrict__ X,
                                   const float* __restrict__ W,
                                   int n) {
    __shared__ alignas(16) float Wsh[KC * NOUT];
    const float4* X4 = X ? (const float4*)X : g_h4;
    int node = blockIdx.x * 256 + threadIdx.x;

    unsigned long long acc2[NOUT / 2];
#pragma unroll
    for (int j = 0; j < NOUT / 2; j++) acc2[j] = 0ull;   // f32x2(0,0)

    for (int k0 = 0; k0 < K; k0 += KC) {
        __syncthreads();
        for (int i = threadIdx.x; i < KC * NOUT; i += 256)
            Wsh[i] = W[k0 * NOUT + i];
        __syncthreads();

        if (node < n) {
            for (int kb = 0; kb < KC; kb += 8) {
                float4 a = X4[(size_t)node * (K / 4) + (size_t)(k0 + kb) / 4];
                float4 b = X4[(size_t)node * (K / 4) + (size_t)(k0 + kb) / 4 + 1];
                float xr[8] = {a.x, a.y, a.z, a.w, b.x, b.y, b.z, b.w};
#pragma unroll
                for (int kk = 0; kk < 8; kk++) {
                    unsigned long long x2 = pack_f32x2(xr[kk], xr[kk]);
                    const ulonglong2* wrow2 =
                        (const ulonglong2*)&Wsh[(kb + kk) * NOUT];
#pragma unroll
                    for (int j = 0; j < NOUT / 4; j++) {
                        ulonglong2 w = wrow2[j];         // LDS.128 broadcast
                        fma_f32x2(acc2[2 * j + 0], x2, w.x);
                        fma_f32x2(acc2[2 * j + 1], x2, w.y);
                    }
                }
            }
        }
    }

    if (node < n) {
        float dv = g_dinv[node];
#pragma unroll
        for (int j = 0; j < NOUT; j += 4) {
            float v0, v1, v2, v3;
            unpack_f32x2(v0, v1, acc2[j / 2 + 0]);
            unpack_f32x2(v2, v3, acc2[j / 2 + 1]);
            float4 v;
            v.x = v0 * dv; v.y = v1 * dv; v.z = v2 * dv; v.w = v3 * dv;
            g_scaled4[((size_t)node * NOUT + j) / 4] = v;
        }
    }
}

// ---------------- fused pull-aggregate + finalize -----------------------------
// h[n] = relu(dinv[n] * (sum_{e in CSR[n]} scaled[src_e] + scaled[n]) + bias)
// CH threads cooperate on one node (one float4 column each). Edge loop unrolled
// x8 for MLP. No atomics, no zero pass, no separate finalize.
template <int NOUT>
__global__ void aggregate_kernel(const float* __restrict__ bias, int n) {
    constexpr int CH = NOUT / 4;                 // threads per node
    constexpr int NPB = 256 / CH;                // nodes per block
    int node = blockIdx.x * NPB + threadIdx.x / CH;
    int c = threadIdx.x % CH;
    if (node >= n) return;

    int start = g_off[node];
    int end = start + g_deg[node];

    float4 acc = g_scaled4[(size_t)node * CH + c];   // self-loop term

    int e = start;
    for (; e + 8 <= end; e += 8) {
        int sidx[8];
#pragma unroll
        for (int u = 0; u < 8; u++) sidx[u] = g_csr_src[e + u];
        float4 v[8];
#pragma unroll
        for (int u = 0; u < 8; u++) v[u] = g_scaled4[(size_t)sidx[u] * CH + c];
#pragma unroll
        for (int u = 0; u < 8; u++) {
            acc.x += v[u].x; acc.y += v[u].y; acc.z += v[u].z; acc.w += v[u].w;
        }
    }
    for (; e < end; e++) {
        int s = g_csr_src[e];
        float4 v = g_scaled4[(size_t)s * CH + c];
        acc.x += v.x; acc.y += v.y; acc.z += v.z; acc.w += v.w;
    }

    float dv = g_dinv[node];
    float4 b = ((const float4*)bias)[c];
    float4 r;
    r.x = fmaxf(fmaf(dv, acc.x, b.x), 0.0f);
    r.y = fmaxf(fmaf(dv, acc.y, b.y), 0.0f);
    r.z = fmaxf(fmaf(dv, acc.z, b.z), 0.0f);
    r.w = fmaxf(fmaf(dv, acc.w, b.w), 0.0f);
    g_h4[(size_t)node * CH + c] = r;
}

// ---------------- pooling (deterministic two-stage) ---------------------------
__global__ void pool_partial_kernel(int n) {
    __shared__ float s[256];
    const float* h = (const float*)g_h4;
    int f = threadIdx.x & 15;
    int grp = threadIdx.x >> 4;
    int chunk = (n + POOL_BLOCKS - 1) / POOL_BLOCKS;
    int start = blockIdx.x * chunk;
    int end = min(start + chunk, n);
    float sum = 0.0f;
    for (int node = start + grp; node < end; node += 16)
        sum += h[(size_t)node * 16 + f];
    s[threadIdx.x] = sum;
    __syncthreads();
    for (int off = 128; off >= 16; off >>= 1) {
        if (threadIdx.x < off) s[threadIdx.x] += s[threadIdx.x + off];
        __syncthreads();
    }
    if (threadIdx.x < 16) g_partial[blockIdx.x * 16 + threadIdx.x] = s[threadIdx.x];
}

// pooled -> relu(pooled@Wf+bf) -> @Ws+bs -> log_softmax
__global__ void final_mlp_kernel(const float* __restrict__ Wf, const float* __restrict__ bf,
                                 const float* __restrict__ Ws, const float* __restrict__ bs,
                                 float* __restrict__ out, int n) {
    __shared__ float pooled[16];
    __shared__ float hidden[8];
    __shared__ float scores[10];
    int t = threadIdx.x;   // 32 threads
    if (t < 16) {
        float sum = 0.0f;
        for (int b = 0; b < POOL_BLOCKS; b++) sum += g_partial[b * 16 + t];
        pooled[t] = sum / (float)n;
    }
    __syncthreads();
    if (t < 8) {
        float a = bf[t];
        for (int k = 0; k < 16; k++) a = fmaf(pooled[k], Wf[k * 8 + t], a);
        hidden[t] = fmaxf(a, 0.0f);
    }
    __syncthreads();
    if (t < 10) {
        float a = bs[t];
        for (int k = 0; k < 8; k++) a = fmaf(hidden[k], Ws[k * 10 + t], a);
        scores[t] = a;
    }
    __syncthreads();
    if (t == 0) {
        float m = scores[0];
        for (int j = 1; j < 10; j++) m = fmaxf(m, scores[j]);
        float sum = 0.0f;
        for (int j = 0; j < 10; j++) sum += expf(scores[j] - m);
        float lse = m + logf(sum);
        for (int j = 0; j < 10; j++) out[j] = scores[j] - lse;
    }
}

// ---------------- launch ------------------------------------------------------
extern "C" void kernel_launch(void* const* d_in, const int* in_sizes, int n_in,
                              void* d_out, int out_size) {
    const float* features = (const float*)d_in[0];
    const int*   ei       = (const int*)d_in[1];   // int32 (JAX default int width)
    const float* W1 = (const float*)d_in[2];  const float* b1 = (const float*)d_in[3];
    const float* W2 = (const float*)d_in[4];  const float* b2 = (const float*)d_in[5];
    const float* W3 = (const float*)d_in[6];  const float* b3 = (const float*)d_in[7];
    const float* Wf = (const float*)d_in[8];  const float* bf = (const float*)d_in[9];
    const float* Ws = (const float*)d_in[10]; const float* bs = (const float*)d_in[11];

    int N = in_sizes[0] / 256;
    int E = in_sizes[1] / 2;

    int nbN = (N + 255) / 256;
    int nbE = (E + 255) / 256;
    int nbScan = (N + SCAN_B - 1) / SCAN_B;

    // ---- CSR build (once per launch, reused by all 3 layers) ----
    zero_deg_kernel<<<nbN, 256>>>(N);
    deg_count_kernel<<<nbE, 256>>>(ei, E);
    make_dinv_kernel<<<nbN, 256>>>(N);
    scan1_kernel<<<nbScan, SCAN_B>>>(N);
    scan2_kernel<<<1, 128>>>(nbScan);
    scan3_kernel<<<nbScan, SCAN_B>>>(N);
    csr_fill_kernel<<<nbE, 256>>>(ei, E);

    // ---- layer 1: 256 -> 64 ----
    gemm_scaled_kernel<256, 64, 128><<<nbN, 256>>>(features, W1, N);
    aggregate_kernel<64><<<(N * 16 + 255) / 256, 256>>>(b1, N);

    // ---- layer 2: 64 -> 32 ----
    gemm_scaled_kernel<64, 32, 64><<<nbN, 256>>>(nullptr, W2, N);
    aggregate_kernel<32><<<(N * 8 + 255) / 256, 256>>>(b2, N);

    // ---- layer 3: 32 -> 16 ----
    gemm_scaled_kernel<32, 16, 32><<<nbN, 256>>>(nullptr, W3, N);
    aggregate_kernel<16><<<(N * 4 + 255) / 256, 256>>>(b3, N);

    // ---- pooling + MLP head ----
    pool_partial_kernel<<<POOL_BLOCKS, 256>>>(N);
    final_mlp_kernel<<<1, 32>>>(Wf, bf, Ws, bs, (float*)d_out, N);
}

// round 6
// speedup vs baseline: 1.7438x; 1.0799x over previous
#include <cuda_runtime.h>
#include <math.h>

// Problem constants (fixed shapes for this problem)
#define NMAX 100000
#define EMAX 3200000
#define POOL_BLOCKS 128
#define SCAN_B 1024

// ---------------- scratch (device globals; no allocation allowed) ------------
__device__ int    g_deg[NMAX];                       // in-degree (int)
__device__ int    g_off[NMAX];                       // CSR exclusive offsets
__device__ int    g_cursor[NMAX];                    // fill cursors
__device__ int    g_csr_src[EMAX];                   // src ids, grouped by dst
__device__ int    g_blocksum[128];                   // scan partials
__device__ float  g_dinv[NMAX];                      // rsqrt(deg+1)
__device__ uint4  g_scaledb[(size_t)NMAX * 8];       // (x@W)*dinv as bf16 (8 bf16 / uint4)
__device__ float4 g_h4     [(size_t)NMAX * 16];      // layer output (fp32)
__device__ float  g_partial[POOL_BLOCKS * 16];

// ---------------- packed helpers ---------------------------------------------
__device__ __forceinline__ unsigned long long pack_f32x2(float lo, float hi) {
    unsigned long long r;
    asm("mov.b64 %0, {%1, %2};" : "=l"(r) : "f"(lo), "f"(hi));
    return r;
}
__device__ __forceinline__ void fma_f32x2(unsigned long long& d,
                                          unsigned long long a,
                                          unsigned long long b) {
    asm("fma.rn.f32x2 %0, %1, %2, %0;" : "+l"(d) : "l"(a), "l"(b));
}
__device__ __forceinline__ void unpack_f32x2(float& lo, float& hi, unsigned long long v) {
    asm("mov.b64 {%0, %1}, %2;" : "=f"(lo), "=f"(hi) : "l"(v));
}
// pack two fp32 -> bf16x2 (lo in low half, hi in high half)
__device__ __forceinline__ unsigned cvt_bf16x2(float lo, float hi) {
    unsigned r;
    asm("cvt.rn.bf16x2.f32 %0, %1, %2;" : "=r"(r) : "f"(hi), "f"(lo));
    return r;
}
// accumulate bf16x2 into two fp32 (bf16 -> f32 is a 16-bit shift)
__device__ __forceinline__ void add_bf2(float& a, float& b, unsigned p) {
    a += __uint_as_float(p << 16);
    b += __uint_as_float(p & 0xffff0000u);
}

// ---------------- degree / CSR construction ----------------------------------
__global__ void zero_deg_kernel(int n) {
    int i = blockIdx.x * 256 + threadIdx.x;
    if (i < n) g_deg[i] = 0;
}

__global__ void deg_count_kernel(const int* __restrict__ ei, int E) {
    int e = blockIdx.x * 256 + threadIdx.x;
    if (e < E) atomicAdd(&g_deg[ei[E + e]], 1);
}

__global__ void make_dinv_kernel(int n) {
    int i = blockIdx.x * 256 + threadIdx.x;
    if (i < n) g_dinv[i] = rsqrtf((float)g_deg[i] + 1.0f);
}

__global__ void scan1_kernel(int n) {
    __shared__ int sh[SCAN_B];
    int i = blockIdx.x * SCAN_B + threadIdx.x;
    int v = (i < n) ? g_deg[i] : 0;
    sh[threadIdx.x] = v;
    __syncthreads();
    for (int off = 1; off < SCAN_B; off <<= 1) {
        int t = (threadIdx.x >= off) ? sh[threadIdx.x - off] : 0;
        __syncthreads();
        sh[threadIdx.x] += t;
        __syncthreads();
    }
    if (i < n) g_off[i] = sh[threadIdx.x] - v;          // exclusive
    if (threadIdx.x == SCAN_B - 1) g_blocksum[blockIdx.x] = sh[SCAN_B - 1];
}

__global__ void scan2_kernel(int nb) {
    __shared__ int sh[128];
    int v = (threadIdx.x < nb) ? g_blocksum[threadIdx.x] : 0;
    sh[threadIdx.x] = v;
    __syncthreads();
    for (int off = 1; off < 128; off <<= 1) {
        int t = (threadIdx.x >= off) ? sh[threadIdx.x - off] : 0;
        __syncthreads();
        sh[threadIdx.x] += t;
        __syncthreads();
    }
    if (threadIdx.x < nb) g_blocksum[threadIdx.x] = sh[threadIdx.x] - v;  // exclusive
}

__global__ void scan3_kernel(int n) {
    int i = blockIdx.x * SCAN_B + threadIdx.x;
    if (i < n) {
        int o = g_off[i] + g_blocksum[blockIdx.x];
        g_off[i] = o;
        g_cursor[i] = o;
    }
}

__global__ void csr_fill_kernel(const int* __restrict__ ei, int E) {
    int e = blockIdx.x * 256 + threadIdx.x;
    if (e < E) {
        int s = ei[e];
        int d = ei[E + e];
        int pos = atomicAdd(&g_cursor[d], 1);
        g_csr_src[pos] = s;
    }
}

// ---------------- GEMM + scale + bf16-pack epilogue ---------------------------
// scaledb[node,:] = bf16((X[node,:] @ W) * dinv[node])
// Packed f32x2 math; W staged in shared, read as 128-bit broadcast.
// X == nullptr means "read from g_h4".
template <int K, int NOUT, int KC>
__global__ void gemm_scaled_kernel(const float* __restrict__ X,
                                   const float* __restrict__ W,
                                   int n) {
    __shared__ alignas(16) float Wsh[KC * NOUT];
    const float4* X4 = X ? (const float4*)X : g_h4;
    int node = blockIdx.x * 256 + threadIdx.x;

    unsigned long long acc2[NOUT / 2];
#pragma unroll
    for (int j = 0; j < NOUT / 2; j++) acc2[j] = 0ull;   // f32x2(0,0)

    for (int k0 = 0; k0 < K; k0 += KC) {
        __syncthreads();
        for (int i = threadIdx.x; i < KC * NOUT; i += 256)
            Wsh[i] = W[k0 * NOUT + i];
        __syncthreads();

        if (node < n) {
            for (int kb = 0; kb < KC; kb += 8) {
                float4 a = X4[(size_t)node * (K / 4) + (size_t)(k0 + kb) / 4];
                float4 b = X4[(size_t)node * (K / 4) + (size_t)(k0 + kb) / 4 + 1];
                float xr[8] = {a.x, a.y, a.z, a.w, b.x, b.y, b.z, b.w};
#pragma unroll
                for (int kk = 0; kk < 8; kk++) {
                    unsigned long long x2 = pack_f32x2(xr[kk], xr[kk]);
                    const ulonglong2* wrow2 =
                        (const ulonglong2*)&Wsh[(kb + kk) * NOUT];
#pragma unroll
                    for (int j = 0; j < NOUT / 4; j++) {
                        ulonglong2 w = wrow2[j];         // LDS.128 broadcast
                        fma_f32x2(acc2[2 * j + 0], x2, w.x);
                        fma_f32x2(acc2[2 * j + 1], x2, w.y);
                    }
                }
            }
        }
    }

    if (node < n) {
        float dv = g_dinv[node];
#pragma unroll
        for (int q = 0; q < NOUT / 8; q++) {      // one uint4 = 8 bf16
            unsigned r[4];
#pragma unroll
            for (int t = 0; t < 4; t++) {
                float lo, hi;
                unpack_f32x2(lo, hi, acc2[4 * q + t]);
                r[t] = cvt_bf16x2(lo * dv, hi * dv);
            }
            uint4 o = make_uint4(r[0], r[1], r[2], r[3]);
            g_scaledb[(size_t)node * (NOUT / 8) + q] = o;
        }
    }
}

// ---------------- fused pull-aggregate + finalize (bf16 gather) ---------------
// h[n] = relu(dinv[n] * (sum_{e in CSR[n]} scaledb[src_e] + scaledb[n]) + bias)
// CH = NOUT/8 threads per node; each thread owns one uint4 (8 bf16 lanes),
// accumulates in fp32, writes fp32 h. No atomics.
template <int NOUT>
__global__ void aggregate_kernel(const float* __restrict__ bias, int n) {
    constexpr int CH = NOUT / 8;                 // threads per node
    constexpr int NPB = 256 / CH;                // nodes per block
    int node = blockIdx.x * NPB + threadIdx.x / CH;
    int c = threadIdx.x % CH;
    if (node >= n) return;

    int start = g_off[node];
    int end = start + g_deg[node];

    float acc[8];
    {
        uint4 sv = g_scaledb[(size_t)node * CH + c];   // self-loop term
        acc[0] = __uint_as_float(sv.x << 16);
        acc[1] = __uint_as_float(sv.x & 0xffff0000u);
        acc[2] = __uint_as_float(sv.y << 16);
        acc[3] = __uint_as_float(sv.y & 0xffff0000u);
        acc[4] = __uint_as_float(sv.z << 16);
        acc[5] = __uint_as_float(sv.z & 0xffff0000u);
        acc[6] = __uint_as_float(sv.w << 16);
        acc[7] = __uint_as_float(sv.w & 0xffff0000u);
    }

    int e = start;
    for (; e + 8 <= end; e += 8) {
        int sidx[8];
#pragma unroll
        for (int u = 0; u < 8; u++) sidx[u] = g_csr_src[e + u];
        uint4 v[8];
#pragma unroll
        for (int u = 0; u < 8; u++) v[u] = g_scaledb[(size_t)sidx[u] * CH + c];
#pragma unroll
        for (int u = 0; u < 8; u++) {
            add_bf2(acc[0], acc[1], v[u].x);
            add_bf2(acc[2], acc[3], v[u].y);
            add_bf2(acc[4], acc[5], v[u].z);
            add_bf2(acc[6], acc[7], v[u].w);
        }
    }
    for (; e < end; e++) {
        uint4 v = g_scaledb[(size_t)g_csr_src[e] * CH + c];
        add_bf2(acc[0], acc[1], v.x);
        add_bf2(acc[2], acc[3], v.y);
        add_bf2(acc[4], acc[5], v.z);
        add_bf2(acc[6], acc[7], v.w);
    }

    float dv = g_dinv[node];
    const float4* b4 = (const float4*)bias;
    float4 bl = b4[c * 2 + 0];
    float4 bh = b4[c * 2 + 1];
    float4 r0, r1;
    r0.x = fmaxf(fmaf(dv, acc[0], bl.x), 0.0f);
    r0.y = fmaxf(fmaf(dv, acc[1], bl.y), 0.0f);
    r0.z = fmaxf(fmaf(dv, acc[2], bl.z), 0.0f);
    r0.w = fmaxf(fmaf(dv, acc[3], bl.w), 0.0f);
    r1.x = fmaxf(fmaf(dv, acc[4], bh.x), 0.0f);
    r1.y = fmaxf(fmaf(dv, acc[5], bh.y), 0.0f);
    r1.z = fmaxf(fmaf(dv, acc[6], bh.z), 0.0f);
    r1.w = fmaxf(fmaf(dv, acc[7], bh.w), 0.0f);
    g_h4[(size_t)node * (NOUT / 4) + c * 2 + 0] = r0;
    g_h4[(size_t)node * (NOUT / 4) + c * 2 + 1] = r1;
}

// ---------------- pooling (deterministic two-stage) ---------------------------
__global__ void pool_partial_kernel(int n) {
    __shared__ float s[256];
    const float* h = (const float*)g_h4;
    int f = threadIdx.x & 15;
    int grp = threadIdx.x >> 4;
    int chunk = (n + POOL_BLOCKS - 1) / POOL_BLOCKS;
    int start = blockIdx.x * chunk;
    int end = min(start + chunk, n);
    float sum = 0.0f;
    for (int node = start + grp; node < end; node += 16)
        sum += h[(size_t)node * 16 + f];
    s[threadIdx.x] = sum;
    __syncthreads();
    for (int off = 128; off >= 16; off >>= 1) {
        if (threadIdx.x < off) s[threadIdx.x] += s[threadIdx.x + off];
        __syncthreads();
    }
    if (threadIdx.x < 16) g_partial[blockIdx.x * 16 + threadIdx.x] = s[threadIdx.x];
}

// pooled -> relu(pooled@Wf+bf) -> @Ws+bs -> log_softmax
__global__ void final_mlp_kernel(const float* __restrict__ Wf, const float* __restrict__ bf,
                                 const float* __restrict__ Ws, const float* __restrict__ bs,
                                 float* __restrict__ out, int n) {
    __shared__ float pooled[16];
    __shared__ float hidden[8];
    __shared__ float scores[10];
    int t = threadIdx.x;   // 32 threads
    if (t < 16) {
        float sum = 0.0f;
        for (int b = 0; b < POOL_BLOCKS; b++) sum += g_partial[b * 16 + t];
        pooled[t] = sum / (float)n;
    }
    __syncthreads();
    if (t < 8) {
        float a = bf[t];
        for (int k = 0; k < 16; k++) a = fmaf(pooled[k], Wf[k * 8 + t], a);
        hidden[t] = fmaxf(a, 0.0f);
    }
    __syncthreads();
    if (t < 10) {
        float a = bs[t];
        for (int k = 0; k < 8; k++) a = fmaf(hidden[k], Ws[k * 10 + t], a);
        scores[t] = a;
    }
    __syncthreads();
    if (t == 0) {
        float m = scores[0];
        for (int j = 1; j < 10; j++) m = fmaxf(m, scores[j]);
        float sum = 0.0f;
        for (int j = 0; j < 10; j++) sum += expf(scores[j] - m);
        float lse = m + logf(sum);
        for (int j = 0; j < 10; j++) out[j] = scores[j] - lse;
    }
}

// ---------------- launch ------------------------------------------------------
extern "C" void kernel_launch(void* const* d_in, const int* in_sizes, int n_in,
                              void* d_out, int out_size) {
    const float* features = (const float*)d_in[0];
    const int*   ei       = (const int*)d_in[1];   // int32 (JAX default int width)
    const float* W1 = (const float*)d_in[2];  const float* b1 = (const float*)d_in[3];
    const float* W2 = (const float*)d_in[4];  const float* b2 = (const float*)d_in[5];
    const float* W3 = (const float*)d_in[6];  const float* b3 = (const float*)d_in[7];
    const float* Wf = (const float*)d_in[8];  const float* bf = (const float*)d_in[9];
    const float* Ws = (const float*)d_in[10]; const float* bs = (const float*)d_in[11];

    int N = in_sizes[0] / 256;
    int E = in_sizes[1] / 2;

    int nbN = (N + 255) / 256;
    int nbE = (E + 255) / 256;
    int nbScan = (N + SCAN_B - 1) / SCAN_B;

    // ---- CSR build (once per launch, reused by all 3 layers) ----
    zero_deg_kernel<<<nbN, 256>>>(N);
    deg_count_kernel<<<nbE, 256>>>(ei, E);
    make_dinv_kernel<<<nbN, 256>>>(N);
    scan1_kernel<<<nbScan, SCAN_B>>>(N);
    scan2_kernel<<<1, 128>>>(nbScan);
    scan3_kernel<<<nbScan, SCAN_B>>>(N);
    csr_fill_kernel<<<nbE, 256>>>(ei, E);

    // ---- layer 1: 256 -> 64 ----
    gemm_scaled_kernel<256, 64, 128><<<nbN, 256>>>(features, W1, N);
    aggregate_kernel<64><<<(N * 8 + 255) / 256, 256>>>(b1, N);

    // ---- layer 2: 64 -> 32 ----
    gemm_scaled_kernel<64, 32, 64><<<nbN, 256>>>(nullptr, W2, N);
    aggregate_kernel<32><<<(N * 4 + 255) / 256, 256>>>(b2, N);

    // ---- layer 3: 32 -> 16 ----
    gemm_scaled_kernel<32, 16, 32><<<nbN, 256>>>(nullptr, W3, N);
    aggregate_kernel<16><<<(N * 2 + 255) / 256, 256>>>(b3, N);

    // ---- pooling + MLP head ----
    pool_partial_kernel<<<POOL_BLOCKS, 256>>>(N);
    final_mlp_kernel<<<1, 32>>>(Wf, bf, Ws, bs, (float*)d_out, N);
}